// round 16
// baseline (speedup 1.0000x reference)
#include <cuda_runtime.h>
#include <cuda_fp16.h>
#include <cstdint>
#include <math.h>

#define B_SZ  2048
#define D_IN  1024
#define D_OUT 2048
#define D_C   256
#define KSPLIT 4

#define GAMMA_F 0.1f
#define RHO_F   0.9f
#define ONE_M_RHO_F 0.1f
#define LR_F    0.009f
#define MOM_F   0.9f
#define EPS_F   1e-8f

// ---- fp32 state / scratch ----
__device__ float g_T  [B_SZ * D_OUT];
__device__ float g_a1 [B_SZ * D_OUT];
__device__ float g_a2 [B_SZ * D_OUT];
__device__ float g_u  [B_SZ * D_C];
__device__ float g_b1 [B_SZ * D_C];
__device__ float g_b2 [B_SZ * D_C];
__device__ float g_VT [D_OUT * D_C];
__device__ float g_c  [B_SZ * D_OUT];       // -2 * inputs @ W^T
__device__ float g_vs [D_C];                // rowsum of V
__device__ float g_d  [D_OUT];              // exact diag of 2*W@W^T
__device__ float g_gp [KSPLIT * B_SZ * D_C];// gu partials, 4 K-slices

// ---- packed fp16 hi/lo operands (per 8-elem group: 4 hi words then 4 lo) ----
__device__ __align__(128) uint32_t g_pkW [D_OUT * D_IN];
__device__ __align__(128) uint32_t g_pkV [D_C * D_OUT];
__device__ __align__(128) uint32_t g_pkVT[D_OUT * D_C];
__device__ __align__(128) uint32_t g_pkIn[B_SZ * D_IN];
__device__ __align__(128) uint32_t g_pkR [D_OUT * D_OUT];   // 2*W@W^T, diag zeroed
__device__ __align__(128) uint32_t g_pkG [B_SZ * D_OUT];
__device__ __align__(128) uint32_t g_pkX0[B_SZ * D_OUT];
__device__ __align__(128) uint32_t g_pkX1[B_SZ * D_OUT];
__device__ __align__(128) uint32_t g_pkU0[B_SZ * D_C];
__device__ __align__(128) uint32_t g_pkU1[B_SZ * D_C];

__device__ __forceinline__ void split2(float x, float y, uint32_t& hi, uint32_t& lo) {
    __half hx = __float2half_rn(x);
    __half hy = __float2half_rn(y);
    float rx = x - __half2float(hx);
    float ry = y - __half2float(hy);
    __half2 H = __halves2half2(hx, hy);
    hi = *reinterpret_cast<uint32_t*>(&H);
    __half2 L = __floats2half2_rn(rx, ry);
    lo = *reinterpret_cast<uint32_t*>(&L);
}

__global__ void transpose_k(const float* __restrict__ src, float* __restrict__ dst,
                            int rows, int cols) {
    __shared__ float t[32][33];
    int bx = blockIdx.x * 32, by = blockIdx.y * 32;
    int x = bx + threadIdx.x;
    #pragma unroll
    for (int j = 0; j < 32; j += 8)
        t[threadIdx.y + j][threadIdx.x] = src[(size_t)(by + threadIdx.y + j) * cols + x];
    __syncthreads();
    int x2 = by + threadIdx.x;
    #pragma unroll
    for (int j = 0; j < 32; j += 8)
        dst[(size_t)(bx + threadIdx.y + j) * rows + x2] = t[threadIdx.x][threadIdx.y + j];
}

__global__ void pack_k(const float* __restrict__ src, uint32_t* __restrict__ dst, int n8) {
    int i = blockIdx.x * blockDim.x + threadIdx.x;
    if (i >= n8) return;
    const float4* s = reinterpret_cast<const float4*>(src) + 2 * (size_t)i;
    float4 v0 = s[0], v1 = s[1];
    uint32_t h0,l0,h1,l1,h2,l2,h3,l3;
    split2(v0.x, v0.y, h0, l0); split2(v0.z, v0.w, h1, l1);
    split2(v1.x, v1.y, h2, l2); split2(v1.z, v1.w, h3, l3);
    uint4* d = reinterpret_cast<uint4*>(dst) + 2 * (size_t)i;
    uint4 H; H.x=h0; H.y=h1; H.z=h2; H.w=h3;
    uint4 L; L.x=l0; L.y=l1; L.z=l2; L.w=l3;
    d[0] = H; d[1] = L;
}

__global__ void vsum_k(const float* __restrict__ V, float* __restrict__ out) {
    __shared__ float red[256];
    int n = blockIdx.x;
    float s = 0.0f;
    for (int k = threadIdx.x; k < D_OUT; k += 256) s += V[(size_t)n * D_OUT + k];
    red[threadIdx.x] = s;
    __syncthreads();
    for (int st = 128; st > 0; st >>= 1) {
        if (threadIdx.x < st) red[threadIdx.x] += red[threadIdx.x + st];
        __syncthreads();
    }
    if (threadIdx.x == 0) out[n] = red[0];
}

// exact diag: d[m] = 2 * sum_k W[m,k]^2
__global__ void wsum_k(const float* __restrict__ W, float* __restrict__ out) {
    __shared__ float red[256];
    int m = blockIdx.x;
    float s = 0.0f;
    for (int k = threadIdx.x; k < D_IN; k += 256) {
        float w = W[(size_t)m * D_IN + k];
        s += w * w;
    }
    red[threadIdx.x] = s;
    __syncthreads();
    for (int st = 128; st > 0; st >>= 1) {
        if (threadIdx.x < st) red[threadIdx.x] += red[threadIdx.x + st];
        __syncthreads();
    }
    if (threadIdx.x == 0) out[m] = 2.0f * red[0];
}

template<int MODE>
__global__ void step0_k(const float* __restrict__ src, float* __restrict__ s,
                        float* __restrict__ a1, float* __restrict__ a2,
                        uint32_t* __restrict__ pk, int n8) {
    int i = blockIdx.x * blockDim.x + threadIdx.x;
    if (i >= n8) return;
    float gv[8];
    if (MODE == 0) {
        const float4* cs = reinterpret_cast<const float4*>(src) + 2 * (size_t)i;
        float4 v0 = cs[0], v1 = cs[1];
        gv[0]=v0.x; gv[1]=v0.y; gv[2]=v0.z; gv[3]=v0.w;
        gv[4]=v1.x; gv[5]=v1.y; gv[6]=v1.z; gv[7]=v1.w;
    } else {
        const float G0 = GAMMA_F * 1.0e-3f * (-0.5f);
        int base = (8 * i) & (D_C - 1);
        #pragma unroll
        for (int j = 0; j < 8; j++) gv[j] = G0 * src[base + j];
    }
    float xs[8], A1[8], A2[8];
    #pragma unroll
    for (int j = 0; j < 8; j++) {
        float g   = gv[j];
        float na1 = ONE_M_RHO_F * g * g;
        float upd = LR_F * g / sqrtf(na1 + EPS_F);
        float na2 = -upd;
        xs[j] = MOM_F * na2 - upd;
        A1[j] = na1; A2[j] = na2;
    }
    float4* so = reinterpret_cast<float4*>(s)  + 2 * (size_t)i;
    float4* o1 = reinterpret_cast<float4*>(a1) + 2 * (size_t)i;
    float4* o2 = reinterpret_cast<float4*>(a2) + 2 * (size_t)i;
    so[0] = make_float4(xs[0],xs[1],xs[2],xs[3]); so[1] = make_float4(xs[4],xs[5],xs[6],xs[7]);
    o1[0] = make_float4(A1[0],A1[1],A1[2],A1[3]); o1[1] = make_float4(A1[4],A1[5],A1[6],A1[7]);
    o2[0] = make_float4(A2[0],A2[1],A2[2],A2[3]); o2[1] = make_float4(A2[4],A2[5],A2[6],A2[7]);
    uint32_t h[4], l[4];
    split2(xs[0],xs[1],h[0],l[0]); split2(xs[2],xs[3],h[1],l[1]);
    split2(xs[4],xs[5],h[2],l[2]); split2(xs[6],xs[7],h[3],l[3]);
    uint4* d = reinterpret_cast<uint4*>(pk) + 2 * (size_t)i;
    uint4 H; H.x=h[0]; H.y=h[1]; H.z=h[2]; H.w=h[3];
    uint4 L; L.x=l[0]; L.y=l[1]; L.z=l[2]; L.w=l[3];
    d[0] = H; d[1] = L;
}

// gu reduction: g = sum of 4 K-slice partials; rmsprop on (u,b1,b2); pack u
__global__ void guredux_k(const float* __restrict__ gp,
                          float* __restrict__ u, float* __restrict__ b1,
                          float* __restrict__ b2, uint32_t* __restrict__ pk, int n8) {
    int i = blockIdx.x * blockDim.x + threadIdx.x;
    if (i >= n8) return;
    float gv[8] = {0,0,0,0,0,0,0,0};
    #pragma unroll
    for (int ks = 0; ks < KSPLIT; ks++) {
        const float4* s0 = reinterpret_cast<const float4*>(gp + (size_t)ks * (B_SZ * D_C))
                         + 2 * (size_t)i;
        float4 p0 = s0[0], p1 = s0[1];
        gv[0]+=p0.x; gv[1]+=p0.y; gv[2]+=p0.z; gv[3]+=p0.w;
        gv[4]+=p1.x; gv[5]+=p1.y; gv[6]+=p1.z; gv[7]+=p1.w;
    }
    float4* su  = reinterpret_cast<float4*>(u)  + 2 * (size_t)i;
    float4* s1p = reinterpret_cast<float4*>(b1) + 2 * (size_t)i;
    float4* s2p = reinterpret_cast<float4*>(b2) + 2 * (size_t)i;
    float4 u0 = su[0], u1 = su[1], a10 = s1p[0], a11 = s1p[1], a20 = s2p[0], a21 = s2p[1];
    float uin[8] = {u0.x,u0.y,u0.z,u0.w,u1.x,u1.y,u1.z,u1.w};
    float a1i[8] = {a10.x,a10.y,a10.z,a10.w,a11.x,a11.y,a11.z,a11.w};
    float a2i[8] = {a20.x,a20.y,a20.z,a20.w,a21.x,a21.y,a21.z,a21.w};
    float uv[8], A1[8], A2[8];
    #pragma unroll
    for (int j = 0; j < 8; j++) {
        float g   = gv[j];
        float na1 = RHO_F * a1i[j] + ONE_M_RHO_F * g * g;
        float upd = LR_F * g / sqrtf(na1 + EPS_F);
        float na2 = MOM_F * a2i[j] - upd;
        uv[j] = uin[j] + MOM_F * na2 - upd;
        A1[j] = na1; A2[j] = na2;
    }
    su[0]  = make_float4(uv[0],uv[1],uv[2],uv[3]); su[1]  = make_float4(uv[4],uv[5],uv[6],uv[7]);
    s1p[0] = make_float4(A1[0],A1[1],A1[2],A1[3]); s1p[1] = make_float4(A1[4],A1[5],A1[6],A1[7]);
    s2p[0] = make_float4(A2[0],A2[1],A2[2],A2[3]); s2p[1] = make_float4(A2[4],A2[5],A2[6],A2[7]);
    uint32_t h[4], l[4];
    split2(uv[0],uv[1],h[0],l[0]); split2(uv[2],uv[3],h[1],l[1]);
    split2(uv[4],uv[5],h[2],l[2]); split2(uv[6],uv[7],h[3],l[3]);
    uint4* d = reinterpret_cast<uint4*>(pk) + 2 * (size_t)i;
    uint4 H; H.x=h[0]; H.y=h[1]; H.z=h[2]; H.w=h[3];
    uint4 L; L.x=l[0]; L.y=l[1]; L.z=l[2]; L.w=l[3];
    d[0] = H; d[1] = L;
}

// ============================ mma helpers ============================

__device__ __forceinline__ uint32_t cvta_smem(const void* p) {
    uint32_t a;
    asm("{ .reg .u64 t; cvta.to.shared.u64 t, %1; cvt.u32.u64 %0, t; }" : "=r"(a) : "l"(p));
    return a;
}

__device__ __forceinline__ void mma_f16(float* c, const uint32_t* a, const uint32_t* b) {
    asm volatile(
        "mma.sync.aligned.m16n8k16.row.col.f32.f16.f16.f32 "
        "{%0,%1,%2,%3}, {%4,%5,%6,%7}, {%8,%9}, {%0,%1,%2,%3};"
        : "+f"(c[0]), "+f"(c[1]), "+f"(c[2]), "+f"(c[3])
        : "r"(a[0]), "r"(a[1]), "r"(a[2]), "r"(a[3]), "r"(b[0]), "r"(b[1]));
}

#define LDSM_X4(R, addr) \
    asm volatile("ldmatrix.sync.aligned.m8n8.x4.shared.b16 {%0,%1,%2,%3}, [%4];" \
        : "=r"((R)[0]), "=r"((R)[1]), "=r"((R)[2]), "=r"((R)[3]) : "r"(addr))

#define CP16(dst, src) \
    asm volatile("cp.async.cg.shared.global [%0], [%1], 16;" :: "r"(dst), "l"(src))

__device__ __forceinline__ void store_pk2(uint32_t* __restrict__ q, int ncols,
                                          int m, int n, float v0, float v1) {
    uint32_t hi, lo; split2(v0, v1, hi, lo);
    uint32_t* p = q + (size_t)m * ncols + ((n >> 3) << 3) + ((n & 7) >> 1);
    p[0] = hi;
    p[4] = lo;
}

// EPI 1: GEMM2: reads p0=x; writes q1=pkG, p2=T
// EPI 2: gx: g = acc + x*d[n] + p4(c) + p0(T); rmsprop p1=x,p2=a1,p3=a2; q1=pkX
// EPI 4: setup M2: pack 2*acc with diag zeroed -> q1
// EPI 5: setup c:  p1 = -2*acc
// EPI 6: gu partial: p1[idx] = acc (raw fp32)
template<int EPI>
__device__ __forceinline__ void epi_pair(float a0, float a1, int m, int n, int Nout,
                                         const float* __restrict__ p0,
                                         const float* __restrict__ p4,
                                         const float* __restrict__ pd,
                                         float* __restrict__ p1,
                                         float* __restrict__ p2,
                                         float* __restrict__ p3,
                                         uint32_t* __restrict__ q1)
{
    const size_t idx = (size_t)m * (size_t)Nout + (size_t)n;
    if (EPI == 6) {
        float2 o; o.x = a0; o.y = a1;
        *reinterpret_cast<float2*>(&p1[idx]) = o;
    } else if (EPI == 4) {
        float v0 = 2.0f * a0, v1 = 2.0f * a1;
        if (m == n)     v0 = 0.0f;
        if (m == n + 1) v1 = 0.0f;
        store_pk2(q1, Nout, m, n, v0, v1);
    } else if (EPI == 5) {
        float2 o; o.x = -2.0f * a0; o.y = -2.0f * a1;
        *reinterpret_cast<float2*>(&p1[idx]) = o;
    } else if (EPI == 1) {
        float2 xv = *reinterpret_cast<const float2*>(&p0[idx]);
        float G0, G1; float2 T;
        {
            float da = sqrtf(xv.x * xv.x + 1e-6f);
            float ex = expf(-a0);
            G0  = GAMMA_F * da * (-0.5f * ex);
            T.x = (GAMMA_F * (1.0f + ex) * 0.5f + GAMMA_F * 0.1f) * (xv.x / da);
        }
        {
            float da = sqrtf(xv.y * xv.y + 1e-6f);
            float ex = expf(-a1);
            G1  = GAMMA_F * da * (-0.5f * ex);
            T.y = (GAMMA_F * (1.0f + ex) * 0.5f + GAMMA_F * 0.1f) * (xv.y / da);
        }
        store_pk2(q1, Nout, m, n, G0, G1);
        *reinterpret_cast<float2*>(&p2[idx]) = T;
    } else {   // EPI == 2
        float2 sv  = *reinterpret_cast<const float2*>(&p1[idx]);
        float2 tv = *reinterpret_cast<const float2*>(&p0[idx]);
        float2 cv = *reinterpret_cast<const float2*>(&p4[idx]);
        float2 dv = *reinterpret_cast<const float2*>(&pd[n]);
        float2 g2;
        g2.x = a0 + sv.x * dv.x + cv.x + tv.x;
        g2.y = a1 + sv.y * dv.y + cv.y + tv.y;
        float2 a1v = *reinterpret_cast<const float2*>(&p2[idx]);
        float2 a2v = *reinterpret_cast<const float2*>(&p3[idx]);
        float na1x = RHO_F * a1v.x + ONE_M_RHO_F * g2.x * g2.x;
        float updx = LR_F * g2.x / sqrtf(na1x + EPS_F);
        float na2x = MOM_F * a2v.x - updx;
        float svx  = sv.x + MOM_F * na2x - updx;
        float na1y = RHO_F * a1v.y + ONE_M_RHO_F * g2.y * g2.y;
        float updy = LR_F * g2.y / sqrtf(na1y + EPS_F);
        float na2y = MOM_F * a2v.y - updy;
        float svy  = sv.y + MOM_F * na2y - updy;
        float2 o1; o1.x = svx;  o1.y = svy;
        float2 o2; o2.x = na1x; o2.y = na1y;
        float2 o3; o3.x = na2x; o3.y = na2y;
        *reinterpret_cast<float2*>(&p1[idx]) = o1;
        store_pk2(q1, Nout, m, n, svx, svy);
        *reinterpret_cast<float2*>(&p2[idx]) = o2;
        *reinterpret_cast<float2*>(&p3[idx]) = o3;
    }
}

// ---- shared mainloop: BM=128, BN=NF*64, BK=32, S=3, 512 threads (16 warps 2x8)
struct Frag { float acc[4][4][4]; };   // sized for NF<=4

template<int NMMA, int NF>
__device__ __forceinline__ void mainloop_128(
    const uint32_t* __restrict__ pkA, const uint32_t* __restrict__ pkB,
    int row0, int col0, int kpitch, int koff, int ktiles, uint32_t sbase, Frag& F)
{
    constexpr int S = 3;
    constexpr int BN = NF * 64;
    constexpr int STAGE = (128 + BN) * 128;
    const int tid  = threadIdx.x;
    const int lane = tid & 31, wid = tid >> 5;
    const int wm = wid >> 3, wn = wid & 7;

    const char* gA = reinterpret_cast<const char*>(pkA) + (size_t)row0 * (4 * kpitch)
                   + (size_t)koff * 128;
    const char* gB = reinterpret_cast<const char*>(pkB) + (size_t)col0 * (4 * kpitch)
                   + (size_t)koff * 128;
    const int pitch = 4 * kpitch;

    auto issue = [&](int kt, int buf) {
        const uint32_t sd = sbase + buf * STAGE;
        const char* sA = gA + kt * 128;
        if (NMMA == 3) {
            #pragma unroll
            for (int i = 0; i < 2; i++) {
                int idx = i * 512 + tid;
                int r = idx >> 3, c = idx & 7;
                uint32_t dst = sd + r * 128 + ((c ^ (r & 7)) << 4);
                CP16(dst, sA + (size_t)r * pitch + (c << 4));
            }
        } else {
            int r = tid >> 2, g = tid & 3;
            int c = 2 * g;
            uint32_t dst = sd + r * 128 + ((c ^ (r & 7)) << 4);
            CP16(dst, sA + (size_t)r * pitch + (c << 4));
        }
        const char* sB = gB + kt * 128;
        if (NMMA >= 2) {
            #pragma unroll
            for (int i = 0; i < NF; i++) {               // BN*8/512 iters
                int idx = i * 512 + tid;
                int r = idx >> 3, c = idx & 7;
                uint32_t dst = sd + 128 * 128 + r * 128 + ((c ^ (r & 7)) << 4);
                CP16(dst, sB + (size_t)r * pitch + (c << 4));
            }
        } else {
            #pragma unroll
            for (int i = 0; i < NF / 2; i++) {           // hi chunks only
                int idx = i * 512 + tid;
                int r = idx >> 2, g = idx & 3;
                int c = 2 * g;
                uint32_t dst = sd + 128 * 128 + r * 128 + ((c ^ (r & 7)) << 4);
                CP16(dst, sB + (size_t)r * pitch + (c << 4));
            }
        }
        asm volatile("cp.async.commit_group;" ::: "memory");
    };

    #pragma unroll
    for (int i = 0; i < 4; i++)
        #pragma unroll
        for (int j = 0; j < NF; j++)
            #pragma unroll
            for (int r = 0; r < 4; r++) F.acc[i][j][r] = 0.0f;

    issue(0, 0);
    issue(1, 1);

    for (int kt = 0; kt < ktiles; kt++) {
        if (kt < ktiles - 1) asm volatile("cp.async.wait_group 1;" ::: "memory");
        else                 asm volatile("cp.async.wait_group 0;" ::: "memory");
        __syncthreads();
        if (kt + 2 < ktiles) issue(kt + 2, (kt + 2) % S);

        const int buf = kt % S;
        const uint32_t sA32 = sbase + buf * STAGE;
        const uint32_t sB32 = sA32 + 128 * 128;

        #pragma unroll
        for (int j = 0; j < 2; j++) {
            uint32_t afh[4][4];
            #pragma unroll
            for (int mf = 0; mf < 4; mf++) {
                int rr = wm * 64 + mf * 16 + (lane & 15);
                int c  = 4 * j + 2 * (lane >> 4);
                uint32_t addr = sA32 + rr * 128 + ((c ^ (rr & 7)) << 4);
                LDSM_X4(afh[mf], addr);
            }
            uint32_t afl[4][4];
            if (NMMA == 3) {
                #pragma unroll
                for (int mf = 0; mf < 4; mf++) {
                    int rr = wm * 64 + mf * 16 + (lane & 15);
                    int c  = 4 * j + 1 + 2 * (lane >> 4);
                    uint32_t addr = sA32 + rr * 128 + ((c ^ (rr & 7)) << 4);
                    LDSM_X4(afl[mf], addr);
                }
            }
            constexpr int NB = (NMMA >= 2) ? 2 : 1;
            uint32_t bfr[NB][NF][2];
            #pragma unroll
            for (int hl = 0; hl < NB; hl++)
                #pragma unroll
                for (int p = 0; p < NF / 2; p++) {
                    uint32_t q[4];
                    int rr = wn * (NF * 8) + (2 * p + (lane >> 4)) * 8 + (lane & 7);
                    int c  = 4 * j + hl + 2 * ((lane >> 3) & 1);
                    uint32_t addr = sB32 + rr * 128 + ((c ^ (rr & 7)) << 4);
                    LDSM_X4(q, addr);
                    bfr[hl][2 * p    ][0] = q[0]; bfr[hl][2 * p    ][1] = q[1];
                    bfr[hl][2 * p + 1][0] = q[2]; bfr[hl][2 * p + 1][1] = q[3];
                }
            #pragma unroll
            for (int mf = 0; mf < 4; mf++)
                #pragma unroll
                for (int nf = 0; nf < NF; nf++) {
                    mma_f16(F.acc[mf][nf], afh[mf], bfr[0][nf]);
                    if (NMMA >= 2)
                        mma_f16(F.acc[mf][nf], afh[mf], bfr[1][nf]);
                    if (NMMA == 3)
                        mma_f16(F.acc[mf][nf], afl[mf], bfr[0][nf]);
                }
        }
    }
}

template<int EPI, int NF>
__device__ __forceinline__ void run_epi(Frag& F, int row0, int col0, int Nout,
                                        const float* p0, const float* p4, const float* pd,
                                        float* p1, float* p2, float* p3, uint32_t* q1)
{
    const int tid  = threadIdx.x;
    const int lane = tid & 31, wid = tid >> 5;
    const int wm = wid >> 3, wn = wid & 7;
    #pragma unroll
    for (int mf = 0; mf < 4; mf++) {
        #pragma unroll
        for (int nf = 0; nf < NF; nf++) {
            int mlo = row0 + wm * 64 + mf * 16 + (lane >> 2);
            int n   = col0 + wn * (NF * 8) + nf * 8 + ((lane & 3) << 1);
            epi_pair<EPI>(F.acc[mf][nf][0], F.acc[mf][nf][1], mlo,     n, Nout, p0, p4, pd, p1, p2, p3, q1);
            epi_pair<EPI>(F.acc[mf][nf][2], F.acc[mf][nf][3], mlo + 8, n, Nout, p0, p4, pd, p1, p2, p3, q1);
        }
    }
}

// GEMM2: s = u@V, EPI 1.  grid 128 (BN=256)
__global__ __launch_bounds__(512, 1)
void gemm2_k(const uint32_t* __restrict__ pkU, const uint32_t* __restrict__ pkVT,
             const float* __restrict__ x, float* __restrict__ pT,
             uint32_t* __restrict__ pkG)
{
    extern __shared__ __align__(1024) char smem[];
    Frag F;
    int col0 = (blockIdx.x & 7) * 256, row0 = (blockIdx.x >> 3) * 128;
    mainloop_128<2,4>(pkU, pkVT, row0, col0, D_C, 0, D_C / 32, cvta_smem(smem), F);
    run_epi<1,4>(F, row0, col0, D_OUT, x, nullptr, nullptr, nullptr, pT, nullptr, pkG);
}

// merged gx + gu, uniform ~1024-HMMA/warp CTAs:
//   blocks [0,256)   = gx, BN=128 (EPI2, 1-term on R), 64 k-tiles
//   blocks [256,320) = gu, BN=256, K/4 split (EPI6, 2-term), 16 k-tiles
__global__ __launch_bounds__(512, 1)
void gemm34_k(const uint32_t* __restrict__ pkX, const uint32_t* __restrict__ pkR,
              const uint32_t* __restrict__ pkG, const uint32_t* __restrict__ pkV,
              const float* __restrict__ pT, const float* __restrict__ pc,
              const float* __restrict__ pd,
              float* __restrict__ x,  float* __restrict__ a1, float* __restrict__ a2,
              uint32_t* __restrict__ pkXw,
              float* __restrict__ gp)
{
    extern __shared__ __align__(1024) char smem[];
    Frag F;
    if (blockIdx.x < 256) {
        int col0 = (blockIdx.x & 15) * 128, row0 = (blockIdx.x >> 4) * 128;
        mainloop_128<1,2>(pkX, pkR, row0, col0, D_OUT, 0, D_OUT / 32, cvta_smem(smem), F);
        run_epi<2,2>(F, row0, col0, D_OUT, pT, pc, pd, x, a1, a2, pkXw);
    } else {
        int b = blockIdx.x - 256;
        int ks = b >> 4;                      // K slice 0..3
        int row0 = (b & 15) * 128;
        mainloop_128<2,4>(pkG, pkV, row0, 0, D_OUT, ks * 16, 16, cvta_smem(smem), F);
        run_epi<6,4>(F, row0, 0, D_C, nullptr, nullptr, nullptr,
                     gp + (size_t)ks * (B_SZ * D_C), nullptr, nullptr, nullptr);
    }
}

// merged setup: blocks [0,128) = R = 2*W@W^T off-diag (EPI4, 3-term),
// [128,256) = c (EPI5, 3-term); K=1024, BN=256
__global__ __launch_bounds__(512, 1)
void setup_k(const uint32_t* __restrict__ pkW, const uint32_t* __restrict__ pkIn,
             uint32_t* __restrict__ pkR, float* __restrict__ pc)
{
    extern __shared__ __align__(1024) char smem[];
    Frag F;
    const bool rolec = blockIdx.x >= 128;
    int b = rolec ? blockIdx.x - 128 : blockIdx.x;
    int col0 = (b & 7) * 256, row0 = (b >> 3) * 128;
    const uint32_t* pkA = rolec ? pkIn : pkW;
    mainloop_128<3,4>(pkA, pkW, row0, col0, D_IN, 0, D_IN / 32, cvta_smem(smem), F);
    if (!rolec)
        run_epi<4,4>(F, row0, col0, D_OUT, nullptr, nullptr, nullptr, nullptr, nullptr, nullptr, pkR);
    else
        run_epi<5,4>(F, row0, col0, D_OUT, nullptr, nullptr, nullptr, pc, nullptr, nullptr, nullptr);
}

// ============================================================================

extern "C" void kernel_launch(void* const* d_in, const int* in_sizes, int n_in,
                              void* d_out, int out_size)
{
    (void)in_sizes; (void)n_in; (void)out_size;
    const float* inputs = (const float*)d_in[0];
    const float* W      = (const float*)d_in[1];
    const float* V      = (const float*)d_in[2];
    float* x = (float*)d_out;

    float *pT, *pa1, *pa2, *pu, *pb1, *pb2, *pVT, *pc, *pvs, *pd, *gp;
    uint32_t *kW, *kV, *kVT, *kIn, *kR, *kG, *kX[2], *kU[2];
    cudaGetSymbolAddress((void**)&pT,  g_T);
    cudaGetSymbolAddress((void**)&pa1, g_a1);
    cudaGetSymbolAddress((void**)&pa2, g_a2);
    cudaGetSymbolAddress((void**)&pu,  g_u);
    cudaGetSymbolAddress((void**)&pb1, g_b1);
    cudaGetSymbolAddress((void**)&pb2, g_b2);
    cudaGetSymbolAddress((void**)&pVT, g_VT);
    cudaGetSymbolAddress((void**)&pc,  g_c);
    cudaGetSymbolAddress((void**)&pvs, g_vs);
    cudaGetSymbolAddress((void**)&pd,  g_d);
    cudaGetSymbolAddress((void**)&gp,  g_gp);
    cudaGetSymbolAddress((void**)&kW,  g_pkW);
    cudaGetSymbolAddress((void**)&kV,  g_pkV);
    cudaGetSymbolAddress((void**)&kVT, g_pkVT);
    cudaGetSymbolAddress((void**)&kIn, g_pkIn);
    cudaGetSymbolAddress((void**)&kR,  g_pkR);
    cudaGetSymbolAddress((void**)&kG,  g_pkG);
    cudaGetSymbolAddress((void**)&kX[0], g_pkX0);
    cudaGetSymbolAddress((void**)&kX[1], g_pkX1);
    cudaGetSymbolAddress((void**)&kU[0], g_pkU0);
    cudaGetSymbolAddress((void**)&kU[1], g_pkU1);

    constexpr int SMEM = 3 * (128 + 256) * 128;   // 147456 (max stage set)
    cudaFuncSetAttribute(gemm2_k,  cudaFuncAttributeMaxDynamicSharedMemorySize, SMEM);
    cudaFuncSetAttribute(gemm34_k, cudaFuncAttributeMaxDynamicSharedMemorySize, SMEM);
    cudaFuncSetAttribute(setup_k,  cudaFuncAttributeMaxDynamicSharedMemorySize, SMEM);

    const int TPB = 256;

    // ---- setup: transpose/pack; exact diag; R (3-term) + c (3-term) ----
    transpose_k<<<dim3(D_OUT / 32, D_C / 32), dim3(32, 8)>>>(V, pVT, D_C, D_OUT);
    pack_k<<<(D_OUT * D_IN / 8 + TPB - 1) / TPB, TPB>>>(W,      kW,  D_OUT * D_IN / 8);
    pack_k<<<(D_C * D_OUT / 8 + TPB - 1) / TPB, TPB>>>(V,       kV,  D_C * D_OUT / 8);
    pack_k<<<(D_OUT * D_C / 8 + TPB - 1) / TPB, TPB>>>(pVT,     kVT, D_OUT * D_C / 8);
    pack_k<<<(B_SZ * D_IN / 8 + TPB - 1) / TPB, TPB>>>(inputs,  kIn, B_SZ * D_IN / 8);
    wsum_k<<<D_OUT, 256>>>(W, pd);

    setup_k<<<256, 512, SMEM>>>(kW, kIn, kR, pc);

    // ---- step 0: x from g=c ; u from g = G0 * rowsum(V) broadcast ----
    vsum_k<<<D_C, 256>>>(V, pvs);
    step0_k<0><<<(B_SZ * D_OUT / 8 + TPB - 1) / TPB, TPB>>>(
        pc, x, pa1, pa2, kX[0], B_SZ * D_OUT / 8);
    step0_k<1><<<(B_SZ * D_C / 8 + TPB - 1) / TPB, TPB>>>(
        pvs, pu, pb1, pb2, kU[0], B_SZ * D_C / 8);

    // ---- steps 1..9: gemm2 ; uniform-subdivided gx+gu ; guredux ----
    for (int s = 1; s < 10; s++) {
        const int rd = (s - 1) & 1, wr = s & 1;
        gemm2_k<<<128, 512, SMEM>>>(kU[rd], kVT, x, pT, kG);
        gemm34_k<<<320, 512, SMEM>>>(kX[rd], kR, kG, kV, pT, pc, pd,
                                     x, pa1, pa2, kX[wr], gp);
        guredux_k<<<(B_SZ * D_C / 8 + TPB - 1) / TPB, TPB>>>(
            gp, pu, pb1, pb2, kU[wr], B_SZ * D_C / 8);
    }
}

// round 17
// speedup vs baseline: 1.1132x; 1.1132x over previous
#include <cuda_runtime.h>
#include <cuda_fp16.h>
#include <cstdint>
#include <math.h>

#define B_SZ  2048
#define D_IN  1024
#define D_OUT 2048
#define D_C   256

#define GAMMA_F 0.1f
#define RHO_F   0.9f
#define ONE_M_RHO_F 0.1f
#define LR_F    0.009f
#define MOM_F   0.9f
#define EPS_F   1e-8f

// ---- fp32 state / scratch ----
__device__ float g_T  [B_SZ * D_OUT];
__device__ float g_a1 [B_SZ * D_OUT];
__device__ float g_a2 [B_SZ * D_OUT];
__device__ float g_u  [B_SZ * D_C];
__device__ float g_b1 [B_SZ * D_C];
__device__ float g_b2 [B_SZ * D_C];
__device__ float g_VT [D_OUT * D_C];
__device__ float g_c  [B_SZ * D_OUT];       // -2 * inputs @ W^T
__device__ float g_vs [D_C];                // rowsum of V
__device__ float g_d  [D_OUT];              // exact diag of 2*W@W^T

// ---- packed fp16 hi/lo operands (per 8-elem group: 4 hi words then 4 lo) ----
__device__ __align__(128) uint32_t g_pkW [D_OUT * D_IN];
__device__ __align__(128) uint32_t g_pkV [D_C * D_OUT];
__device__ __align__(128) uint32_t g_pkVT[D_OUT * D_C];
__device__ __align__(128) uint32_t g_pkIn[B_SZ * D_IN];
__device__ __align__(128) uint32_t g_pkR [D_OUT * D_OUT];   // 2*W@W^T, diag zeroed
__device__ __align__(128) uint32_t g_pkG [B_SZ * D_OUT];
__device__ __align__(128) uint32_t g_pkX0[B_SZ * D_OUT];
__device__ __align__(128) uint32_t g_pkX1[B_SZ * D_OUT];
__device__ __align__(128) uint32_t g_pkU0[B_SZ * D_C];
__device__ __align__(128) uint32_t g_pkU1[B_SZ * D_C];

__device__ __forceinline__ void split2(float x, float y, uint32_t& hi, uint32_t& lo) {
    __half hx = __float2half_rn(x);
    __half hy = __float2half_rn(y);
    float rx = x - __half2float(hx);
    float ry = y - __half2float(hy);
    __half2 H = __halves2half2(hx, hy);
    hi = *reinterpret_cast<uint32_t*>(&H);
    __half2 L = __floats2half2_rn(rx, ry);
    lo = *reinterpret_cast<uint32_t*>(&L);
}

__global__ void transpose_k(const float* __restrict__ src, float* __restrict__ dst,
                            int rows, int cols) {
    __shared__ float t[32][33];
    int bx = blockIdx.x * 32, by = blockIdx.y * 32;
    int x = bx + threadIdx.x;
    #pragma unroll
    for (int j = 0; j < 32; j += 8)
        t[threadIdx.y + j][threadIdx.x] = src[(size_t)(by + threadIdx.y + j) * cols + x];
    __syncthreads();
    int x2 = by + threadIdx.x;
    #pragma unroll
    for (int j = 0; j < 32; j += 8)
        dst[(size_t)(bx + threadIdx.y + j) * rows + x2] = t[threadIdx.x][threadIdx.y + j];
}

__global__ void pack_k(const float* __restrict__ src, uint32_t* __restrict__ dst, int n8) {
    int i = blockIdx.x * blockDim.x + threadIdx.x;
    if (i >= n8) return;
    const float4* s = reinterpret_cast<const float4*>(src) + 2 * (size_t)i;
    float4 v0 = s[0], v1 = s[1];
    uint32_t h0,l0,h1,l1,h2,l2,h3,l3;
    split2(v0.x, v0.y, h0, l0); split2(v0.z, v0.w, h1, l1);
    split2(v1.x, v1.y, h2, l2); split2(v1.z, v1.w, h3, l3);
    uint4* d = reinterpret_cast<uint4*>(dst) + 2 * (size_t)i;
    uint4 H; H.x=h0; H.y=h1; H.z=h2; H.w=h3;
    uint4 L; L.x=l0; L.y=l1; L.z=l2; L.w=l3;
    d[0] = H; d[1] = L;
}

__global__ void vsum_k(const float* __restrict__ V, float* __restrict__ out) {
    __shared__ float red[256];
    int n = blockIdx.x;
    float s = 0.0f;
    for (int k = threadIdx.x; k < D_OUT; k += 256) s += V[(size_t)n * D_OUT + k];
    red[threadIdx.x] = s;
    __syncthreads();
    for (int st = 128; st > 0; st >>= 1) {
        if (threadIdx.x < st) red[threadIdx.x] += red[threadIdx.x + st];
        __syncthreads();
    }
    if (threadIdx.x == 0) out[n] = red[0];
}

// exact diag: d[m] = 2 * sum_k W[m,k]^2
__global__ void wsum_k(const float* __restrict__ W, float* __restrict__ out) {
    __shared__ float red[256];
    int m = blockIdx.x;
    float s = 0.0f;
    for (int k = threadIdx.x; k < D_IN; k += 256) {
        float w = W[(size_t)m * D_IN + k];
        s += w * w;
    }
    red[threadIdx.x] = s;
    __syncthreads();
    for (int st = 128; st > 0; st >>= 1) {
        if (threadIdx.x < st) red[threadIdx.x] += red[threadIdx.x + st];
        __syncthreads();
    }
    if (threadIdx.x == 0) out[m] = 2.0f * red[0];
}

template<int MODE>
__global__ void step0_k(const float* __restrict__ src, float* __restrict__ s,
                        float* __restrict__ a1, float* __restrict__ a2,
                        uint32_t* __restrict__ pk, int n8) {
    int i = blockIdx.x * blockDim.x + threadIdx.x;
    if (i >= n8) return;
    float gv[8];
    if (MODE == 0) {
        const float4* cs = reinterpret_cast<const float4*>(src) + 2 * (size_t)i;
        float4 v0 = cs[0], v1 = cs[1];
        gv[0]=v0.x; gv[1]=v0.y; gv[2]=v0.z; gv[3]=v0.w;
        gv[4]=v1.x; gv[5]=v1.y; gv[6]=v1.z; gv[7]=v1.w;
    } else {
        const float G0 = GAMMA_F * 1.0e-3f * (-0.5f);
        int base = (8 * i) & (D_C - 1);
        #pragma unroll
        for (int j = 0; j < 8; j++) gv[j] = G0 * src[base + j];
    }
    float xs[8], A1[8], A2[8];
    #pragma unroll
    for (int j = 0; j < 8; j++) {
        float g   = gv[j];
        float na1 = ONE_M_RHO_F * g * g;
        float upd = LR_F * g / sqrtf(na1 + EPS_F);
        float na2 = -upd;
        xs[j] = MOM_F * na2 - upd;
        A1[j] = na1; A2[j] = na2;
    }
    float4* so = reinterpret_cast<float4*>(s)  + 2 * (size_t)i;
    float4* o1 = reinterpret_cast<float4*>(a1) + 2 * (size_t)i;
    float4* o2 = reinterpret_cast<float4*>(a2) + 2 * (size_t)i;
    so[0] = make_float4(xs[0],xs[1],xs[2],xs[3]); so[1] = make_float4(xs[4],xs[5],xs[6],xs[7]);
    o1[0] = make_float4(A1[0],A1[1],A1[2],A1[3]); o1[1] = make_float4(A1[4],A1[5],A1[6],A1[7]);
    o2[0] = make_float4(A2[0],A2[1],A2[2],A2[3]); o2[1] = make_float4(A2[4],A2[5],A2[6],A2[7]);
    uint32_t h[4], l[4];
    split2(xs[0],xs[1],h[0],l[0]); split2(xs[2],xs[3],h[1],l[1]);
    split2(xs[4],xs[5],h[2],l[2]); split2(xs[6],xs[7],h[3],l[3]);
    uint4* d = reinterpret_cast<uint4*>(pk) + 2 * (size_t)i;
    uint4 H; H.x=h[0]; H.y=h[1]; H.z=h[2]; H.w=h[3];
    uint4 L; L.x=l[0]; L.y=l[1]; L.z=l[2]; L.w=l[3];
    d[0] = H; d[1] = L;
}

// ============================ mma helpers ============================

__device__ __forceinline__ uint32_t cvta_smem(const void* p) {
    uint32_t a;
    asm("{ .reg .u64 t; cvta.to.shared.u64 t, %1; cvt.u32.u64 %0, t; }" : "=r"(a) : "l"(p));
    return a;
}

__device__ __forceinline__ void mma_f16(float* c, const uint32_t* a, const uint32_t* b) {
    asm volatile(
        "mma.sync.aligned.m16n8k16.row.col.f32.f16.f16.f32 "
        "{%0,%1,%2,%3}, {%4,%5,%6,%7}, {%8,%9}, {%0,%1,%2,%3};"
        : "+f"(c[0]), "+f"(c[1]), "+f"(c[2]), "+f"(c[3])
        : "r"(a[0]), "r"(a[1]), "r"(a[2]), "r"(a[3]), "r"(b[0]), "r"(b[1]));
}

#define LDSM_X4(R, addr) \
    asm volatile("ldmatrix.sync.aligned.m8n8.x4.shared.b16 {%0,%1,%2,%3}, [%4];" \
        : "=r"((R)[0]), "=r"((R)[1]), "=r"((R)[2]), "=r"((R)[3]) : "r"(addr))

#define CP16(dst, src) \
    asm volatile("cp.async.cg.shared.global [%0], [%1], 16;" :: "r"(dst), "l"(src))

__device__ __forceinline__ void store_pk2(uint32_t* __restrict__ q, int ncols,
                                          int m, int n, float v0, float v1) {
    uint32_t hi, lo; split2(v0, v1, hi, lo);
    uint32_t* p = q + (size_t)m * ncols + ((n >> 3) << 3) + ((n & 7) >> 1);
    p[0] = hi;
    p[4] = lo;
}

// EPI 1: GEMM2: reads p0=x; writes q1=pkG, p2=T
// EPI 2: gx: g = acc + x*d[n] + p4(c) + p0(T); rmsprop p1=x,p2=a1,p3=a2; q1=pkX
// EPI 3: gu: g = acc; rmsprop p1=u,p2=b1,p3=b2; q1=pkU
// EPI 4: setup M2: pack 2*acc with diag zeroed -> q1
// EPI 5: setup c:  p1 = -2*acc
template<int EPI>
__device__ __forceinline__ void epi_pair(float a0, float a1, int m, int n, int Nout,
                                         const float* __restrict__ p0,
                                         const float* __restrict__ p4,
                                         const float* __restrict__ pd,
                                         float* __restrict__ p1,
                                         float* __restrict__ p2,
                                         float* __restrict__ p3,
                                         uint32_t* __restrict__ q1)
{
    const size_t idx = (size_t)m * (size_t)Nout + (size_t)n;
    if (EPI == 4) {
        float v0 = 2.0f * a0, v1 = 2.0f * a1;
        if (m == n)     v0 = 0.0f;
        if (m == n + 1) v1 = 0.0f;
        store_pk2(q1, Nout, m, n, v0, v1);
    } else if (EPI == 5) {
        float2 o; o.x = -2.0f * a0; o.y = -2.0f * a1;
        *reinterpret_cast<float2*>(&p1[idx]) = o;
    } else if (EPI == 1) {
        float2 xv = *reinterpret_cast<const float2*>(&p0[idx]);
        float G0, G1; float2 T;
        {
            float da = sqrtf(xv.x * xv.x + 1e-6f);
            float ex = expf(-a0);
            G0  = GAMMA_F * da * (-0.5f * ex);
            T.x = (GAMMA_F * (1.0f + ex) * 0.5f + GAMMA_F * 0.1f) * (xv.x / da);
        }
        {
            float da = sqrtf(xv.y * xv.y + 1e-6f);
            float ex = expf(-a1);
            G1  = GAMMA_F * da * (-0.5f * ex);
            T.y = (GAMMA_F * (1.0f + ex) * 0.5f + GAMMA_F * 0.1f) * (xv.y / da);
        }
        store_pk2(q1, Nout, m, n, G0, G1);
        *reinterpret_cast<float2*>(&p2[idx]) = T;
    } else {   // EPI == 2 or 3
        float2 sv  = *reinterpret_cast<const float2*>(&p1[idx]);
        float2 g2;
        if (EPI == 2) {
            float2 tv = *reinterpret_cast<const float2*>(&p0[idx]);
            float2 cv = *reinterpret_cast<const float2*>(&p4[idx]);
            float2 dv = *reinterpret_cast<const float2*>(&pd[n]);
            g2.x = a0 + sv.x * dv.x + cv.x + tv.x;
            g2.y = a1 + sv.y * dv.y + cv.y + tv.y;
        } else {
            g2.x = a0; g2.y = a1;
        }
        float2 a1v = *reinterpret_cast<const float2*>(&p2[idx]);
        float2 a2v = *reinterpret_cast<const float2*>(&p3[idx]);
        float na1x = RHO_F * a1v.x + ONE_M_RHO_F * g2.x * g2.x;
        float updx = LR_F * g2.x / sqrtf(na1x + EPS_F);
        float na2x = MOM_F * a2v.x - updx;
        float svx  = sv.x + MOM_F * na2x - updx;
        float na1y = RHO_F * a1v.y + ONE_M_RHO_F * g2.y * g2.y;
        float updy = LR_F * g2.y / sqrtf(na1y + EPS_F);
        float na2y = MOM_F * a2v.y - updy;
        float svy  = sv.y + MOM_F * na2y - updy;
        float2 o1; o1.x = svx;  o1.y = svy;
        float2 o2; o2.x = na1x; o2.y = na1y;
        float2 o3; o3.x = na2x; o3.y = na2y;
        *reinterpret_cast<float2*>(&p1[idx]) = o1;
        store_pk2(q1, Nout, m, n, svx, svy);
        *reinterpret_cast<float2*>(&p2[idx]) = o2;
        *reinterpret_cast<float2*>(&p3[idx]) = o3;
    }
}

// ---- shared mainloop: BM=128, BN=256, BK=32, S=3, 512 threads (16 warps 2x8)
struct Frag { float acc[4][4][4]; };

template<int NMMA>
__device__ __forceinline__ void mainloop_128x256(
    const uint32_t* __restrict__ pkA, const uint32_t* __restrict__ pkB,
    int row0, int col0, int kpitch, int ktiles, uint32_t sbase, Frag& F)
{
    constexpr int S = 3;
    constexpr int STAGE = (128 + 256) * 128;
    const int tid  = threadIdx.x;
    const int lane = tid & 31, wid = tid >> 5;
    const int wm = wid >> 3, wn = wid & 7;

    const char* gA = reinterpret_cast<const char*>(pkA) + (size_t)row0 * (4 * kpitch);
    const char* gB = reinterpret_cast<const char*>(pkB) + (size_t)col0 * (4 * kpitch);
    const int pitch = 4 * kpitch;

    auto issue = [&](int kt, int buf) {
        const uint32_t sd = sbase + buf * STAGE;
        const char* sA = gA + kt * 128;
        if (NMMA == 3) {
            #pragma unroll
            for (int i = 0; i < 2; i++) {
                int idx = i * 512 + tid;
                int r = idx >> 3, c = idx & 7;
                uint32_t dst = sd + r * 128 + ((c ^ (r & 7)) << 4);
                CP16(dst, sA + (size_t)r * pitch + (c << 4));
            }
        } else {
            int r = tid >> 2, g = tid & 3;
            int c = 2 * g;
            uint32_t dst = sd + r * 128 + ((c ^ (r & 7)) << 4);
            CP16(dst, sA + (size_t)r * pitch + (c << 4));
        }
        const char* sB = gB + kt * 128;
        if (NMMA >= 2) {
            #pragma unroll
            for (int i = 0; i < 4; i++) {
                int idx = i * 512 + tid;
                int r = idx >> 3, c = idx & 7;
                uint32_t dst = sd + 128 * 128 + r * 128 + ((c ^ (r & 7)) << 4);
                CP16(dst, sB + (size_t)r * pitch + (c << 4));
            }
        } else {
            #pragma unroll
            for (int i = 0; i < 2; i++) {
                int idx = i * 512 + tid;
                int r = idx >> 2, g = idx & 3;
                int c = 2 * g;
                uint32_t dst = sd + 128 * 128 + r * 128 + ((c ^ (r & 7)) << 4);
                CP16(dst, sB + (size_t)r * pitch + (c << 4));
            }
        }
        asm volatile("cp.async.commit_group;" ::: "memory");
    };

    #pragma unroll
    for (int i = 0; i < 4; i++)
        #pragma unroll
        for (int j = 0; j < 4; j++)
            #pragma unroll
            for (int r = 0; r < 4; r++) F.acc[i][j][r] = 0.0f;

    issue(0, 0);
    issue(1, 1);

    for (int kt = 0; kt < ktiles; kt++) {
        if (kt < ktiles - 1) asm volatile("cp.async.wait_group 1;" ::: "memory");
        else                 asm volatile("cp.async.wait_group 0;" ::: "memory");
        __syncthreads();
        if (kt + 2 < ktiles) issue(kt + 2, (kt + 2) % S);

        const int buf = kt % S;
        const uint32_t sA32 = sbase + buf * STAGE;
        const uint32_t sB32 = sA32 + 128 * 128;

        #pragma unroll
        for (int j = 0; j < 2; j++) {
            uint32_t afh[4][4];
            #pragma unroll
            for (int mf = 0; mf < 4; mf++) {
                int rr = wm * 64 + mf * 16 + (lane & 15);
                int c  = 4 * j + 2 * (lane >> 4);
                uint32_t addr = sA32 + rr * 128 + ((c ^ (rr & 7)) << 4);
                LDSM_X4(afh[mf], addr);
            }
            uint32_t afl[4][4];
            if (NMMA == 3) {
                #pragma unroll
                for (int mf = 0; mf < 4; mf++) {
                    int rr = wm * 64 + mf * 16 + (lane & 15);
                    int c  = 4 * j + 1 + 2 * (lane >> 4);
                    uint32_t addr = sA32 + rr * 128 + ((c ^ (rr & 7)) << 4);
                    LDSM_X4(afl[mf], addr);
                }
            }
            constexpr int NB = (NMMA >= 2) ? 2 : 1;
            uint32_t bfr[NB][4][2];
            #pragma unroll
            for (int hl = 0; hl < NB; hl++)
                #pragma unroll
                for (int p = 0; p < 2; p++) {
                    uint32_t q[4];
                    int rr = wn * 32 + (2 * p + (lane >> 4)) * 8 + (lane & 7);
                    int c  = 4 * j + hl + 2 * ((lane >> 3) & 1);
                    uint32_t addr = sB32 + rr * 128 + ((c ^ (rr & 7)) << 4);
                    LDSM_X4(q, addr);
                    bfr[hl][2 * p    ][0] = q[0]; bfr[hl][2 * p    ][1] = q[1];
                    bfr[hl][2 * p + 1][0] = q[2]; bfr[hl][2 * p + 1][1] = q[3];
                }
            #pragma unroll
            for (int mf = 0; mf < 4; mf++)
                #pragma unroll
                for (int nf = 0; nf < 4; nf++) {
                    mma_f16(F.acc[mf][nf], afh[mf], bfr[0][nf]);
                    if (NMMA >= 2)
                        mma_f16(F.acc[mf][nf], afh[mf], bfr[1][nf]);
                    if (NMMA == 3)
                        mma_f16(F.acc[mf][nf], afl[mf], bfr[0][nf]);
                }
        }
    }
}

template<int EPI>
__device__ __forceinline__ void run_epi(Frag& F, int row0, int col0, int Nout,
                                        const float* p0, const float* p4, const float* pd,
                                        float* p1, float* p2, float* p3, uint32_t* q1)
{
    const int tid  = threadIdx.x;
    const int lane = tid & 31, wid = tid >> 5;
    const int wm = wid >> 3, wn = wid & 7;
    #pragma unroll
    for (int mf = 0; mf < 4; mf++) {
        #pragma unroll
        for (int nf = 0; nf < 4; nf++) {
            int mlo = row0 + wm * 64 + mf * 16 + (lane >> 2);
            int n   = col0 + wn * 32 + nf * 8 + ((lane & 3) << 1);
            epi_pair<EPI>(F.acc[mf][nf][0], F.acc[mf][nf][1], mlo,     n, Nout, p0, p4, pd, p1, p2, p3, q1);
            epi_pair<EPI>(F.acc[mf][nf][2], F.acc[mf][nf][3], mlo + 8, n, Nout, p0, p4, pd, p1, p2, p3, q1);
        }
    }
}

// GEMM2: s = u@V, EPI 1.  grid 128
__global__ __launch_bounds__(512, 1)
void gemm2_k(const uint32_t* __restrict__ pkU, const uint32_t* __restrict__ pkVT,
             const float* __restrict__ x, float* __restrict__ pT,
             uint32_t* __restrict__ pkG)
{
    extern __shared__ __align__(1024) char smem[];
    Frag F;
    int col0 = (blockIdx.x & 7) * 256, row0 = (blockIdx.x >> 3) * 128;
    mainloop_128x256<2>(pkU, pkVT, row0, col0, D_C, D_C / 32, cvta_smem(smem), F);
    run_epi<1>(F, row0, col0, D_OUT, x, nullptr, nullptr, nullptr, pT, nullptr, pkG);
}

// merged gx + gu: 144 UNIFORM CTAs (one wave on 148 SMs).
//   blocks [0,128)   = gx (NMMA=1 on R), 64 kt, 2048 MMA-units/warp
//   blocks [128,144) = gu (NMMA=1 on V hi), 64 kt, 2048 units — u updated in-place
__global__ __launch_bounds__(512, 1)
void gemm34_k(const uint32_t* __restrict__ pkX, const uint32_t* __restrict__ pkR,
              const uint32_t* __restrict__ pkG, const uint32_t* __restrict__ pkV,
              const float* __restrict__ pT, const float* __restrict__ pc,
              const float* __restrict__ pd,
              float* __restrict__ x,  float* __restrict__ a1, float* __restrict__ a2,
              uint32_t* __restrict__ pkXw,
              float* __restrict__ u,  float* __restrict__ b1, float* __restrict__ b2,
              uint32_t* __restrict__ pkUw)
{
    extern __shared__ __align__(1024) char smem[];
    Frag F;
    if (blockIdx.x < 128) {
        int col0 = (blockIdx.x & 7) * 256, row0 = (blockIdx.x >> 3) * 128;
        mainloop_128x256<1>(pkX, pkR, row0, col0, D_OUT, D_OUT / 32, cvta_smem(smem), F);
        run_epi<2>(F, row0, col0, D_OUT, pT, pc, pd, x, a1, a2, pkXw);
    } else {
        int row0 = (blockIdx.x - 128) * 128;
        mainloop_128x256<1>(pkG, pkV, row0, 0, D_OUT, D_OUT / 32, cvta_smem(smem), F);
        run_epi<3>(F, row0, 0, D_C, nullptr, nullptr, nullptr, u, b1, b2, pkUw);
    }
}

// merged setup: blocks [0,128) = R = 2*W@W^T off-diag (EPI4, 3-term),
// [128,256) = c (EPI5, 3-term); K=1024
__global__ __launch_bounds__(512, 1)
void setup_k(const uint32_t* __restrict__ pkW, const uint32_t* __restrict__ pkIn,
             uint32_t* __restrict__ pkR, float* __restrict__ pc)
{
    extern __shared__ __align__(1024) char smem[];
    Frag F;
    const bool rolec = blockIdx.x >= 128;
    int b = rolec ? blockIdx.x - 128 : blockIdx.x;
    int col0 = (b & 7) * 256, row0 = (b >> 3) * 128;
    const uint32_t* pkA = rolec ? pkIn : pkW;
    mainloop_128x256<3>(pkA, pkW, row0, col0, D_IN, D_IN / 32, cvta_smem(smem), F);
    if (!rolec)
        run_epi<4>(F, row0, col0, D_OUT, nullptr, nullptr, nullptr, nullptr, nullptr, nullptr, pkR);
    else
        run_epi<5>(F, row0, col0, D_OUT, nullptr, nullptr, nullptr, pc, nullptr, nullptr, nullptr);
}

// ============================================================================

extern "C" void kernel_launch(void* const* d_in, const int* in_sizes, int n_in,
                              void* d_out, int out_size)
{
    (void)in_sizes; (void)n_in; (void)out_size;
    const float* inputs = (const float*)d_in[0];
    const float* W      = (const float*)d_in[1];
    const float* V      = (const float*)d_in[2];
    float* x = (float*)d_out;

    float *pT, *pa1, *pa2, *pu, *pb1, *pb2, *pVT, *pc, *pvs, *pd;
    uint32_t *kW, *kV, *kVT, *kIn, *kR, *kG, *kX[2], *kU[2];
    cudaGetSymbolAddress((void**)&pT,  g_T);
    cudaGetSymbolAddress((void**)&pa1, g_a1);
    cudaGetSymbolAddress((void**)&pa2, g_a2);
    cudaGetSymbolAddress((void**)&pu,  g_u);
    cudaGetSymbolAddress((void**)&pb1, g_b1);
    cudaGetSymbolAddress((void**)&pb2, g_b2);
    cudaGetSymbolAddress((void**)&pVT, g_VT);
    cudaGetSymbolAddress((void**)&pc,  g_c);
    cudaGetSymbolAddress((void**)&pvs, g_vs);
    cudaGetSymbolAddress((void**)&pd,  g_d);
    cudaGetSymbolAddress((void**)&kW,  g_pkW);
    cudaGetSymbolAddress((void**)&kV,  g_pkV);
    cudaGetSymbolAddress((void**)&kVT, g_pkVT);
    cudaGetSymbolAddress((void**)&kIn, g_pkIn);
    cudaGetSymbolAddress((void**)&kR,  g_pkR);
    cudaGetSymbolAddress((void**)&kG,  g_pkG);
    cudaGetSymbolAddress((void**)&kX[0], g_pkX0);
    cudaGetSymbolAddress((void**)&kX[1], g_pkX1);
    cudaGetSymbolAddress((void**)&kU[0], g_pkU0);
    cudaGetSymbolAddress((void**)&kU[1], g_pkU1);

    constexpr int SMEM = 3 * (128 + 256) * 128;   // 147456
    cudaFuncSetAttribute(gemm2_k,  cudaFuncAttributeMaxDynamicSharedMemorySize, SMEM);
    cudaFuncSetAttribute(gemm34_k, cudaFuncAttributeMaxDynamicSharedMemorySize, SMEM);
    cudaFuncSetAttribute(setup_k,  cudaFuncAttributeMaxDynamicSharedMemorySize, SMEM);

    const int TPB = 256;

    // ---- setup: transpose/pack; exact diag; R (3-term) + c (3-term) ----
    transpose_k<<<dim3(D_OUT / 32, D_C / 32), dim3(32, 8)>>>(V, pVT, D_C, D_OUT);
    pack_k<<<(D_OUT * D_IN / 8 + TPB - 1) / TPB, TPB>>>(W,      kW,  D_OUT * D_IN / 8);
    pack_k<<<(D_C * D_OUT / 8 + TPB - 1) / TPB, TPB>>>(V,       kV,  D_C * D_OUT / 8);
    pack_k<<<(D_OUT * D_C / 8 + TPB - 1) / TPB, TPB>>>(pVT,     kVT, D_OUT * D_C / 8);
    pack_k<<<(B_SZ * D_IN / 8 + TPB - 1) / TPB, TPB>>>(inputs,  kIn, B_SZ * D_IN / 8);
    wsum_k<<<D_OUT, 256>>>(W, pd);

    setup_k<<<256, 512, SMEM>>>(kW, kIn, kR, pc);

    // ---- step 0: x from g=c ; u from g = G0 * rowsum(V) broadcast ----
    vsum_k<<<D_C, 256>>>(V, pvs);
    step0_k<0><<<(B_SZ * D_OUT / 8 + TPB - 1) / TPB, TPB>>>(
        pc, x, pa1, pa2, kX[0], B_SZ * D_OUT / 8);
    step0_k<1><<<(B_SZ * D_C / 8 + TPB - 1) / TPB, TPB>>>(
        pvs, pu, pb1, pb2, kU[0], B_SZ * D_C / 8);

    // ---- steps 1..9: gemm2 ; single-wave uniform gx+gu (no redux) ----
    for (int s = 1; s < 10; s++) {
        const int rd = (s - 1) & 1, wr = s & 1;
        gemm2_k<<<128, 512, SMEM>>>(kU[rd], kVT, x, pT, kG);
        gemm34_k<<<144, 512, SMEM>>>(kX[rd], kR, kG, kV, pT, pc, pd,
                                     x, pa1, pa2, kX[wr],
                                     pu, pb1, pb2, kU[wr]);
    }
}